// round 1
// baseline (speedup 1.0000x reference)
#include <cuda_runtime.h>

#define N_TOK   2048
#define D_MODEL 1024
#define H_PKM   4
#define HALFD   256
#define NKEYS   256
#define KNN     16
#define NEXP    16
#define DOUT    1024
#define HC      8              // H_PKM * 2
#define SCOLS   2048           // HC * NKEYS

// ---------------- scratch (device globals; no allocation allowed) ----------------
__device__ float g_M[D_MODEL * SCOLS];        // combined W_q @ keys^T   (8 MB)
__device__ float g_scores[N_TOK * SCOLS];     // per-token sub-key scores (16 MB)
__device__ float g_x[N_TOK * D_MODEL];        // residual + pkm output   (8 MB)
__device__ float g_w[N_TOK * H_PKM * KNN];    // pkm softmax weights
__device__ int   g_idx[N_TOK * H_PKM * KNN];  // pkm value indices
__device__ int   g_cnt[NEXP];                 // expert bucket counts
__device__ int   g_btok[NEXP * N_TOK];        // expert bucket token ids
__device__ float g_bw[NEXP * N_TOK];          // expert bucket gate weights
__device__ float g_g[N_TOK * 2];              // top-2 gate weights
__device__ int   g_gi[N_TOK * 2];             // top-2 expert ids

__device__ __forceinline__ float neg_inf() { return __int_as_float(0xff800000); }

// ---------------- generic 128x128x8 fp32 GEMM ----------------
// TB=0: B is KxN row-major.  TB=1: B is NxK row-major (transposed on load).
// M, N assumed multiples of 128; K multiple of 8. blockIdx.z offsets pointers.
template <int TB>
__global__ void __launch_bounds__(256)
sgemm128(const float* __restrict__ A, const float* __restrict__ B,
         float* __restrict__ C, int K, int lda, int ldb, int ldc,
         long zA, long zB, long zC)
{
    A += (long)blockIdx.z * zA;
    B += (long)blockIdx.z * zB;
    C += (long)blockIdx.z * zC;
    const int m0 = blockIdx.y * 128;
    const int n0 = blockIdx.x * 128;

    __shared__ float As[8][128];
    __shared__ float Bs[8][128];

    const int tid = threadIdx.x;
    const int ar = tid >> 1, ac = (tid & 1) << 2;      // A: 128 rows x 8 cols
    const int ty = tid >> 4, tx = tid & 15;            // 16x16 threads, 8x8 micro

    float acc[8][8];
#pragma unroll
    for (int i = 0; i < 8; i++)
#pragma unroll
        for (int j = 0; j < 8; j++) acc[i][j] = 0.f;

    const float* Ap = A + (size_t)(m0 + ar) * lda + ac;

    for (int k0 = 0; k0 < K; k0 += 8) {
        float4 av = *(const float4*)(Ap + k0);
        As[ac + 0][ar] = av.x; As[ac + 1][ar] = av.y;
        As[ac + 2][ar] = av.z; As[ac + 3][ar] = av.w;
        if (TB == 0) {
            const int br = tid >> 5, bc = (tid & 31) << 2;   // 8 rows x 128 cols
            float4 bv = *(const float4*)(B + (size_t)(k0 + br) * ldb + n0 + bc);
            *(float4*)&Bs[br][bc] = bv;
        } else {
            const int br = tid >> 1, bc = (tid & 1) << 2;    // 128 n-rows x 8 k-cols
            float4 bv = *(const float4*)(B + (size_t)(n0 + br) * ldb + k0 + bc);
            Bs[bc + 0][br] = bv.x; Bs[bc + 1][br] = bv.y;
            Bs[bc + 2][br] = bv.z; Bs[bc + 3][br] = bv.w;
        }
        __syncthreads();
#pragma unroll
        for (int kk = 0; kk < 8; kk++) {
            float4 a0 = *(const float4*)&As[kk][ty * 8];
            float4 a1 = *(const float4*)&As[kk][ty * 8 + 4];
            float4 b0 = *(const float4*)&Bs[kk][tx * 8];
            float4 b1 = *(const float4*)&Bs[kk][tx * 8 + 4];
            float a[8] = {a0.x, a0.y, a0.z, a0.w, a1.x, a1.y, a1.z, a1.w};
            float b[8] = {b0.x, b0.y, b0.z, b0.w, b1.x, b1.y, b1.z, b1.w};
#pragma unroll
            for (int i = 0; i < 8; i++)
#pragma unroll
                for (int j = 0; j < 8; j++)
                    acc[i][j] = fmaf(a[i], b[j], acc[i][j]);
        }
        __syncthreads();
    }

    float* Cp = C + (size_t)(m0 + ty * 8) * ldc + n0 + tx * 8;
#pragma unroll
    for (int i = 0; i < 8; i++) {
        float4 c0 = {acc[i][0], acc[i][1], acc[i][2], acc[i][3]};
        float4 c1 = {acc[i][4], acc[i][5], acc[i][6], acc[i][7]};
        *(float4*)(Cp + (size_t)i * ldc) = c0;
        *(float4*)(Cp + (size_t)i * ldc + 4) = c1;
    }
}

// ---------------- PKM top-k: per (token, head) ----------------
__global__ void __launch_bounds__(256) pkm_topk_kernel()
{
    const int n = blockIdx.x;
    const int h = blockIdx.y;
    const int tid = threadIdx.x;

    __shared__ float arr[256];
    __shared__ float rv[256];
    __shared__ int   ri[256];
    __shared__ float v1[KNN], v2[KNN];
    __shared__ int   idx1[KNN], idx2[KNN];
    __shared__ float selv[KNN];
    __shared__ int   seli[KNN];

    const float* srow = g_scores + (size_t)n * SCOLS;

    // stage 1: top-16 of each sub-key score vector (c = 0, 1)
    for (int c = 0; c < 2; c++) {
        arr[tid] = srow[(h * 2 + c) * NKEYS + tid];
        __syncthreads();
        for (int r = 0; r < KNN; r++) {
            rv[tid] = arr[tid]; ri[tid] = tid;
            __syncthreads();
            for (int s = 128; s > 0; s >>= 1) {
                if (tid < s) {
                    float ov = rv[tid + s]; int oi = ri[tid + s];
                    if (ov > rv[tid] || (ov == rv[tid] && oi < ri[tid])) {
                        rv[tid] = ov; ri[tid] = oi;
                    }
                }
                __syncthreads();
            }
            if (tid == 0) {
                int wi = ri[0];
                if (c == 0) { v1[r] = rv[0]; idx1[r] = wi; }
                else        { v2[r] = rv[0]; idx2[r] = wi; }
                arr[wi] = neg_inf();
            }
            __syncthreads();
        }
    }

    // stage 2: top-16 of the 16x16 cartesian candidates
    arr[tid] = v1[tid >> 4] + v2[tid & 15];
    __syncthreads();
    for (int r = 0; r < KNN; r++) {
        rv[tid] = arr[tid]; ri[tid] = tid;
        __syncthreads();
        for (int s = 128; s > 0; s >>= 1) {
            if (tid < s) {
                float ov = rv[tid + s]; int oi = ri[tid + s];
                if (ov > rv[tid] || (ov == rv[tid] && oi < ri[tid])) {
                    rv[tid] = ov; ri[tid] = oi;
                }
            }
            __syncthreads();
        }
        if (tid == 0) {
            selv[r] = rv[0]; seli[r] = ri[0];
            arr[ri[0]] = neg_inf();
        }
        __syncthreads();
    }

    // softmax + emit (selv[0] is the max: selected in descending order)
    if (tid == 0) {
        float m = selv[0], s = 0.f, w[KNN];
#pragma unroll
        for (int r = 0; r < KNN; r++) { w[r] = expf(selv[r] - m); s += w[r]; }
        float inv = 1.f / s;
#pragma unroll
        for (int r = 0; r < KNN; r++) {
            int t = seli[r];
            g_w[(n * H_PKM + h) * KNN + r]   = w[r] * inv;
            g_idx[(n * H_PKM + h) * KNN + r] = idx1[t >> 4] * NKEYS + idx2[t & 15];
        }
    }
}

// ---------------- PKM gather + residual: x = data + sum w*values[idx] ----------------
__global__ void __launch_bounds__(256) pkm_gather_kernel(const float* __restrict__ data,
                                                          const float* __restrict__ values)
{
    const int n = blockIdx.x;
    const int tid = threadIdx.x;           // 256 threads * float4 = 1024 cols
    __shared__ float sw[H_PKM * KNN];
    __shared__ int   sidx[H_PKM * KNN];
    if (tid < H_PKM * KNN) {
        sw[tid]   = g_w[n * H_PKM * KNN + tid];
        sidx[tid] = g_idx[n * H_PKM * KNN + tid];
    }
    __syncthreads();

    float4 acc = *(const float4*)(data + (size_t)n * D_MODEL + tid * 4);
#pragma unroll 4
    for (int r = 0; r < H_PKM * KNN; r++) {
        float w = sw[r];
        float4 v = *(const float4*)(values + (size_t)sidx[r] * D_MODEL + tid * 4);
        acc.x = fmaf(w, v.x, acc.x);
        acc.y = fmaf(w, v.y, acc.y);
        acc.z = fmaf(w, v.z, acc.z);
        acc.w = fmaf(w, v.w, acc.w);
    }
    *(float4*)(g_x + (size_t)n * D_MODEL + tid * 4) = acc;
}

// ---------------- gate: logits, top-2 softmax, expert bucketing ----------------
__global__ void zero_cnt_kernel() { if (threadIdx.x < NEXP) g_cnt[threadIdx.x] = 0; }

__global__ void __launch_bounds__(256) gate_kernel(const float* __restrict__ gate_W,
                                                    const float* __restrict__ gate_b)
{
    const int gwarp = (blockIdx.x * blockDim.x + threadIdx.x) >> 5;
    const int lane = threadIdx.x & 31;
    if (gwarp >= N_TOK) return;
    const int n = gwarp;

    float acc[NEXP];
#pragma unroll
    for (int e = 0; e < NEXP; e++) acc[e] = 0.f;

    const float* xrow = g_x + (size_t)n * D_MODEL;
    for (int d = lane; d < D_MODEL; d += 32) {
        float xv = xrow[d];
        const float4* wr = (const float4*)(gate_W + (size_t)d * NEXP);
#pragma unroll
        for (int q = 0; q < 4; q++) {
            float4 w4 = wr[q];
            acc[q * 4 + 0] = fmaf(xv, w4.x, acc[q * 4 + 0]);
            acc[q * 4 + 1] = fmaf(xv, w4.y, acc[q * 4 + 1]);
            acc[q * 4 + 2] = fmaf(xv, w4.z, acc[q * 4 + 2]);
            acc[q * 4 + 3] = fmaf(xv, w4.w, acc[q * 4 + 3]);
        }
    }
#pragma unroll
    for (int e = 0; e < NEXP; e++)
#pragma unroll
        for (int off = 16; off > 0; off >>= 1)
            acc[e] += __shfl_down_sync(0xffffffffu, acc[e], off);

    if (lane == 0) {
        float v0 = neg_inf(), v1 = neg_inf();
        int i0 = -1, i1 = -1;
#pragma unroll
        for (int e = 0; e < NEXP; e++) {
            float l = acc[e] + gate_b[e];
            if (l > v0)      { v1 = v0; i1 = i0; v0 = l; i0 = e; }
            else if (l > v1) { v1 = l; i1 = e; }
        }
        float t = expf(v1 - v0);
        float gw0 = 1.f / (1.f + t);
        float gw1 = t / (1.f + t);
        g_g[n * 2 + 0] = gw0;  g_gi[n * 2 + 0] = i0;
        g_g[n * 2 + 1] = gw1;  g_gi[n * 2 + 1] = i1;
        int p0 = atomicAdd(&g_cnt[i0], 1);
        g_btok[i0 * N_TOK + p0] = n;  g_bw[i0 * N_TOK + p0] = gw0;
        int p1 = atomicAdd(&g_cnt[i1], 1);
        g_btok[i1 * N_TOK + p1] = n;  g_bw[i1 * N_TOK + p1] = gw1;
    }
}

// ---------------- init output with gated expert biases ----------------
__global__ void __launch_bounds__(256) out_init_kernel(const float* __restrict__ expert_b,
                                                        float* __restrict__ out)
{
    const int n = blockIdx.x;
    const int tid = threadIdx.x;
    float gw0 = g_g[n * 2], gw1 = g_g[n * 2 + 1];
    int e0 = g_gi[n * 2], e1 = g_gi[n * 2 + 1];
    float4 b0 = *(const float4*)(expert_b + (size_t)e0 * DOUT + tid * 4);
    float4 b1 = *(const float4*)(expert_b + (size_t)e1 * DOUT + tid * 4);
    float4 o;
    o.x = gw0 * b0.x + gw1 * b1.x;
    o.y = gw0 * b0.y + gw1 * b1.y;
    o.z = gw0 * b0.z + gw1 * b1.z;
    o.w = gw0 * b0.w + gw1 * b1.w;
    *(float4*)(out + (size_t)n * DOUT + tid * 4) = o;
}

// ---------------- grouped expert GEMM: out[tok] += g * (x[tok] @ W_e) ----------------
__global__ void __launch_bounds__(256) expert_gemm_kernel(const float* __restrict__ expert_W,
                                                           float* __restrict__ out)
{
    const int e = blockIdx.y;
    const int cnt = g_cnt[e];
    const int m0 = blockIdx.z * 128;
    if (m0 >= cnt) return;
    const int n0 = blockIdx.x * 128;

    __shared__ float As[8][128];
    __shared__ float Bs[8][128];
    __shared__ int   s_tok[128];
    __shared__ float s_gw[128];

    const int tid = threadIdx.x;
    if (tid < 128) {
        int mi = m0 + tid;
        int ok = (mi < cnt);
        int src = ok ? mi : 0;
        s_tok[tid] = g_btok[e * N_TOK + src];
        s_gw[tid]  = ok ? g_bw[e * N_TOK + src] : 0.f;
    }
    __syncthreads();

    const int ar = tid >> 1, ac = (tid & 1) << 2;
    const int ty = tid >> 4, tx = tid & 15;
    const int arow = s_tok[ar];
    const float* Ap = g_x + (size_t)arow * D_MODEL + ac;
    const float* W = expert_W + (size_t)e * D_MODEL * DOUT;

    float acc[8][8];
#pragma unroll
    for (int i = 0; i < 8; i++)
#pragma unroll
        for (int j = 0; j < 8; j++) acc[i][j] = 0.f;

    for (int k0 = 0; k0 < D_MODEL; k0 += 8) {
        float4 av = *(const float4*)(Ap + k0);
        As[ac + 0][ar] = av.x; As[ac + 1][ar] = av.y;
        As[ac + 2][ar] = av.z; As[ac + 3][ar] = av.w;
        const int br = tid >> 5, bc = (tid & 31) << 2;
        float4 bv = *(const float4*)(W + (size_t)(k0 + br) * DOUT + n0 + bc);
        *(float4*)&Bs[br][bc] = bv;
        __syncthreads();
#pragma unroll
        for (int kk = 0; kk < 8; kk++) {
            float4 a0 = *(const float4*)&As[kk][ty * 8];
            float4 a1 = *(const float4*)&As[kk][ty * 8 + 4];
            float4 b0 = *(const float4*)&Bs[kk][tx * 8];
            float4 b1 = *(const float4*)&Bs[kk][tx * 8 + 4];
            float a[8] = {a0.x, a0.y, a0.z, a0.w, a1.x, a1.y, a1.z, a1.w};
            float b[8] = {b0.x, b0.y, b0.z, b0.w, b1.x, b1.y, b1.z, b1.w};
#pragma unroll
            for (int i = 0; i < 8; i++)
#pragma unroll
                for (int j = 0; j < 8; j++)
                    acc[i][j] = fmaf(a[i], b[j], acc[i][j]);
        }
        __syncthreads();
    }

#pragma unroll
    for (int i = 0; i < 8; i++) {
        int lm = ty * 8 + i;
        if (m0 + lm < cnt) {
            float gw = s_gw[lm];
            float* op = out + (size_t)s_tok[lm] * DOUT + n0 + tx * 8;
#pragma unroll
            for (int j = 0; j < 8; j++)
                atomicAdd(op + j, gw * acc[i][j]);
        }
    }
}

// ---------------- launch ----------------
extern "C" void kernel_launch(void* const* d_in, const int* in_sizes, int n_in,
                              void* d_out, int out_size)
{
    const float* data     = (const float*)d_in[0];  // [2048,1024]
    const float* W_q      = (const float*)d_in[1];  // [1024,2048]
    const float* keys     = (const float*)d_in[2];  // [4,2,256,256]
    const float* values   = (const float*)d_in[3];  // [65536,1024]
    const float* gate_W   = (const float*)d_in[4];  // [1024,16]
    const float* gate_b   = (const float*)d_in[5];  // [16]
    const float* expert_W = (const float*)d_in[6];  // [16,1024,1024]
    const float* expert_b = (const float*)d_in[7];  // [16,1024]
    float* out = (float*)d_out;                     // [2048,1024]

    float* dM;      cudaGetSymbolAddress((void**)&dM, g_M);
    float* dScores; cudaGetSymbolAddress((void**)&dScores, g_scores);

    zero_cnt_kernel<<<1, 32>>>();

    // combined key projection: M[:, hc*256 + k] = W_q[:, hc] @ keys[hc]^T
    sgemm128<1><<<dim3(2, 8, HC), 256>>>(W_q, keys, dM,
                                         /*K=*/HALFD, /*lda=*/SCOLS, /*ldb=*/HALFD,
                                         /*ldc=*/SCOLS,
                                         /*zA=*/HALFD, /*zB=*/(long)NKEYS * HALFD,
                                         /*zC=*/NKEYS);

    // scores = data @ M   [2048 x 2048], K = 1024
    sgemm128<0><<<dim3(16, 16, 1), 256>>>(data, dM, dScores,
                                          /*K=*/D_MODEL, /*lda=*/D_MODEL,
                                          /*ldb=*/SCOLS, /*ldc=*/SCOLS,
                                          0, 0, 0);

    pkm_topk_kernel<<<dim3(N_TOK, H_PKM), 256>>>();
    pkm_gather_kernel<<<N_TOK, 256>>>(data, values);
    gate_kernel<<<N_TOK / 8, 256>>>(gate_W, gate_b);
    out_init_kernel<<<N_TOK, 256>>>(expert_b, out);
    expert_gemm_kernel<<<dim3(DOUT / 128, NEXP, N_TOK / 128), 256>>>(expert_W, out);
}

// round 4
// speedup vs baseline: 2.1607x; 2.1607x over previous
#include <cuda_runtime.h>
#include <mma.h>

using namespace nvcuda;

#define N_TOK   2048
#define D_MODEL 1024
#define H_PKM   4
#define HALFD   256
#define NKEYS   256
#define KNN     16
#define NEXP    16
#define DOUT    1024
#define HC      8              // H_PKM * 2
#define SCOLS   2048           // HC * NKEYS

// ---------------- scratch (device globals; no allocation allowed) ----------------
__device__ float g_M[D_MODEL * SCOLS];        // combined W_q @ keys^T   (8 MB)
__device__ float g_scores[N_TOK * SCOLS];     // per-token sub-key scores (16 MB)
__device__ float g_x[N_TOK * D_MODEL];        // residual + pkm output   (8 MB)
__device__ float g_w[N_TOK * H_PKM * KNN];    // pkm softmax weights
__device__ int   g_idx[N_TOK * H_PKM * KNN];  // pkm value indices
__device__ int   g_cnt[NEXP];                 // expert bucket counts
__device__ int   g_btok[NEXP * N_TOK];        // expert bucket token ids
__device__ float g_bw[NEXP * N_TOK];          // expert bucket gate weights
__device__ float g_g[N_TOK * 2];              // top-2 gate weights
__device__ int   g_gi[N_TOK * 2];             // top-2 expert ids

__device__ __forceinline__ float neg_inf() { return __int_as_float(0xff800000); }

// ---------------- fp32 SIMT GEMM for the small M-projection only ----------------
// B is NxK row-major (transposed on load). 128x128 tiles, K multiple of 8.
__global__ void __launch_bounds__(256)
sgemm128_tb(const float* __restrict__ A, const float* __restrict__ B,
            float* __restrict__ C, int K, int lda, int ldb, int ldc,
            long zA, long zB, long zC)
{
    A += (long)blockIdx.z * zA;
    B += (long)blockIdx.z * zB;
    C += (long)blockIdx.z * zC;
    const int m0 = blockIdx.y * 128;
    const int n0 = blockIdx.x * 128;

    __shared__ float As[8][128];
    __shared__ float Bs[8][128];

    const int tid = threadIdx.x;
    const int ar = tid >> 1, ac = (tid & 1) << 2;
    const int ty = tid >> 4, tx = tid & 15;

    float acc[8][8];
#pragma unroll
    for (int i = 0; i < 8; i++)
#pragma unroll
        for (int j = 0; j < 8; j++) acc[i][j] = 0.f;

    const float* Ap = A + (size_t)(m0 + ar) * lda + ac;

    for (int k0 = 0; k0 < K; k0 += 8) {
        float4 av = *(const float4*)(Ap + k0);
        As[ac + 0][ar] = av.x; As[ac + 1][ar] = av.y;
        As[ac + 2][ar] = av.z; As[ac + 3][ar] = av.w;
        const int br = tid >> 1, bc = (tid & 1) << 2;
        float4 bv = *(const float4*)(B + (size_t)(n0 + br) * ldb + k0 + bc);
        Bs[bc + 0][br] = bv.x; Bs[bc + 1][br] = bv.y;
        Bs[bc + 2][br] = bv.z; Bs[bc + 3][br] = bv.w;
        __syncthreads();
#pragma unroll
        for (int kk = 0; kk < 8; kk++) {
            float4 a0 = *(const float4*)&As[kk][ty * 8];
            float4 a1 = *(const float4*)&As[kk][ty * 8 + 4];
            float4 b0 = *(const float4*)&Bs[kk][tx * 8];
            float4 b1 = *(const float4*)&Bs[kk][tx * 8 + 4];
            float a[8] = {a0.x, a0.y, a0.z, a0.w, a1.x, a1.y, a1.z, a1.w};
            float b[8] = {b0.x, b0.y, b0.z, b0.w, b1.x, b1.y, b1.z, b1.w};
#pragma unroll
            for (int i = 0; i < 8; i++)
#pragma unroll
                for (int j = 0; j < 8; j++)
                    acc[i][j] = fmaf(a[i], b[j], acc[i][j]);
        }
        __syncthreads();
    }

    float* Cp = C + (size_t)(m0 + ty * 8) * ldc + n0 + tx * 8;
#pragma unroll
    for (int i = 0; i < 8; i++) {
        float4 c0 = {acc[i][0], acc[i][1], acc[i][2], acc[i][3]};
        float4 c1 = {acc[i][4], acc[i][5], acc[i][6], acc[i][7]};
        *(float4*)(Cp + (size_t)i * ldc) = c0;
        *(float4*)(Cp + (size_t)i * ldc + 4) = c1;
    }
}

// ---------------- tf32 wmma helpers ----------------
template <typename Frag>
__device__ __forceinline__ void to_tf32(Frag& f)
{
#pragma unroll
    for (int t = 0; t < f.num_elements; t++) f.x[t] = wmma::__float_to_tf32(f.x[t]);
}

// ---------------- scores GEMM: g_scores = data @ g_M  (tf32 tensor cores) ----------------
// Block 128x128, 8 warps in 4(M)x2(N); warp tile 32x64 = 2x4 m16n16k8 frags.
__global__ void __launch_bounds__(256) wmma_scores_kernel(const float* __restrict__ A)
{
    const int m0 = blockIdx.y * 128;
    const int n0 = blockIdx.x * 128;

    __shared__ float As[128][24];          // 128 x 16 (+pad)
    __shared__ float Bs[16][136];          // 16 x 128 (+pad)

    const int tid = threadIdx.x;
    const int warp = tid >> 5;
    const int wm = warp >> 1;              // 0..3
    const int wn = warp & 1;               // 0..1

    wmma::fragment<wmma::accumulator, 16, 16, 8, float> acc[2][4];
#pragma unroll
    for (int i = 0; i < 2; i++)
#pragma unroll
        for (int j = 0; j < 4; j++) wmma::fill_fragment(acc[i][j], 0.f);

    for (int k0 = 0; k0 < D_MODEL; k0 += 16) {
        // A tile: 128 rows x 16 cols
#pragma unroll
        for (int l = tid; l < 512; l += 256) {
            int m = l >> 2, q = (l & 3) << 2;
            *(float4*)&As[m][q] = *(const float4*)(A + (size_t)(m0 + m) * D_MODEL + k0 + q);
        }
        // B tile: 16 rows x 128 cols from g_M
#pragma unroll
        for (int l = tid; l < 512; l += 256) {
            int kr = l >> 5, nc = (l & 31) << 2;
            *(float4*)&Bs[kr][nc] = *(const float4*)(g_M + (size_t)(k0 + kr) * SCOLS + n0 + nc);
        }
        __syncthreads();

#pragma unroll
        for (int kk = 0; kk < 16; kk += 8) {
            wmma::fragment<wmma::matrix_a, 16, 16, 8, wmma::precision::tf32, wmma::row_major> af[2];
#pragma unroll
            for (int i = 0; i < 2; i++) {
                wmma::load_matrix_sync(af[i], &As[wm * 32 + i * 16][kk], 24);
                to_tf32(af[i]);
            }
            wmma::fragment<wmma::matrix_b, 16, 16, 8, wmma::precision::tf32, wmma::row_major> bf[4];
#pragma unroll
            for (int j = 0; j < 4; j++) {
                wmma::load_matrix_sync(bf[j], &Bs[kk][wn * 64 + j * 16], 136);
                to_tf32(bf[j]);
            }
#pragma unroll
            for (int i = 0; i < 2; i++)
#pragma unroll
                for (int j = 0; j < 4; j++)
                    wmma::mma_sync(acc[i][j], af[i], bf[j], acc[i][j]);
        }
        __syncthreads();
    }

#pragma unroll
    for (int i = 0; i < 2; i++)
#pragma unroll
        for (int j = 0; j < 4; j++)
            wmma::store_matrix_sync(g_scores + (size_t)(m0 + wm * 32 + i * 16) * SCOLS
                                             + n0 + wn * 64 + j * 16,
                                    acc[i][j], SCOLS, wmma::mem_row_major);
}

// ---------------- warp-level argmax ----------------
__device__ __forceinline__ void warp_argmax(float& bv, int& bi)
{
#pragma unroll
    for (int off = 16; off > 0; off >>= 1) {
        float ov = __shfl_xor_sync(0xffffffffu, bv, off);
        int   oi = __shfl_xor_sync(0xffffffffu, bi, off);
        if (ov > bv || (ov == bv && oi < bi)) { bv = ov; bi = oi; }
    }
}

// ---------------- PKM top-k: one warp per (token, head), shuffle-only ----------------
__global__ void __launch_bounds__(256) pkm_topk_warp_kernel()
{
    const int wib  = threadIdx.x >> 5;
    const int lane = threadIdx.x & 31;
    const int gw   = blockIdx.x * 8 + wib;
    const int n = gw >> 2;
    const int h = gw & 3;

    __shared__ float s_v1[8][KNN];
    __shared__ float s_v2[8][KNN];
    __shared__ int   s_i1[8][KNN];
    __shared__ int   s_i2[8][KNN];
    __shared__ int   s_sel[8][KNN];

    const float* srow = g_scores + (size_t)n * SCOLS + (size_t)(h * 2) * NKEYS;
    const float NI = neg_inf();

    // stage 1: top-16 of each 256-wide sub-key score vector
#pragma unroll
    for (int c = 0; c < 2; c++) {
        float v[8];
#pragma unroll
        for (int q = 0; q < 8; q++) v[q] = srow[c * NKEYS + q * 32 + lane];
#pragma unroll
        for (int r = 0; r < KNN; r++) {
            float bv = v[0]; int bq = 0;
#pragma unroll
            for (int q = 1; q < 8; q++)
                if (v[q] > bv) { bv = v[q]; bq = q; }
            int bi = bq * 32 + lane;
            warp_argmax(bv, bi);
            if (lane == 0) {
                if (c == 0) { s_v1[wib][r] = bv; s_i1[wib][r] = bi; }
                else        { s_v2[wib][r] = bv; s_i2[wib][r] = bi; }
            }
            if ((bi & 31) == lane) {
                const int wq = bi >> 5;
#pragma unroll
                for (int q = 0; q < 8; q++)
                    if (q == wq) v[q] = NI;
            }
        }
    }
    __syncwarp();

    // stage 2: top-16 of the 16x16 cartesian candidate sums
    float cv[8];
#pragma unroll
    for (int q = 0; q < 8; q++) {
        int t = q * 32 + lane;
        cv[q] = s_v1[wib][t >> 4] + s_v2[wib][t & 15];
    }
    float top0 = 0.f;
#pragma unroll
    for (int r = 0; r < KNN; r++) {
        float bv = cv[0]; int bq = 0;
#pragma unroll
        for (int q = 1; q < 8; q++)
            if (cv[q] > bv) { bv = cv[q]; bq = q; }
        int bi = bq * 32 + lane;
        warp_argmax(bv, bi);
        if (r == 0) top0 = bv;
        if (lane == r) s_sel[wib][r] = bi;
        if ((bi & 31) == lane) {
            const int wq = bi >> 5;
#pragma unroll
            for (int q = 0; q < 8; q++)
                if (q == wq) cv[q] = NI;
        }
    }
    __syncwarp();

    // softmax over the 16 selected + emit
    float e = 0.f;
    int t = 0;
    if (lane < KNN) {
        t = s_sel[wib][lane];
        float sv = s_v1[wib][t >> 4] + s_v2[wib][t & 15];
        e = __expf(sv - top0);
    }
    float s = e;
#pragma unroll
    for (int off = 16; off > 0; off >>= 1)
        s += __shfl_xor_sync(0xffffffffu, s, off);
    if (lane < KNN) {
        const int o = (n * H_PKM + h) * KNN + lane;
        g_w[o]   = e / s;
        g_idx[o] = s_i1[wib][t >> 4] * NKEYS + s_i2[wib][t & 15];
    }
}

// ---------------- PKM gather + residual: x = data + sum w*values[idx] ----------------
__global__ void __launch_bounds__(256) pkm_gather_kernel(const float* __restrict__ data,
                                                          const float* __restrict__ values)
{
    const int n = blockIdx.x;
    const int tid = threadIdx.x;
    __shared__ float sw[H_PKM * KNN];
    __shared__ int   sidx[H_PKM * KNN];
    if (tid < H_PKM * KNN) {
        sw[tid]   = g_w[n * H_PKM * KNN + tid];
        sidx[tid] = g_idx[n * H_PKM * KNN + tid];
    }
    __syncthreads();

    float4 acc = *(const float4*)(data + (size_t)n * D_MODEL + tid * 4);
#pragma unroll 4
    for (int r = 0; r < H_PKM * KNN; r++) {
        float w = sw[r];
        float4 v = *(const float4*)(values + (size_t)sidx[r] * D_MODEL + tid * 4);
        acc.x = fmaf(w, v.x, acc.x);
        acc.y = fmaf(w, v.y, acc.y);
        acc.z = fmaf(w, v.z, acc.z);
        acc.w = fmaf(w, v.w, acc.w);
    }
    *(float4*)(g_x + (size_t)n * D_MODEL + tid * 4) = acc;
}

// ---------------- gate: logits, top-2 softmax, expert bucketing ----------------
__global__ void zero_cnt_kernel() { if (threadIdx.x < NEXP) g_cnt[threadIdx.x] = 0; }

__global__ void __launch_bounds__(256) gate_kernel(const float* __restrict__ gate_W,
                                                    const float* __restrict__ gate_b)
{
    const int gwarp = (blockIdx.x * blockDim.x + threadIdx.x) >> 5;
    const int lane = threadIdx.x & 31;
    if (gwarp >= N_TOK) return;
    const int n = gwarp;

    float acc[NEXP];
#pragma unroll
    for (int e = 0; e < NEXP; e++) acc[e] = 0.f;

    const float* xrow = g_x + (size_t)n * D_MODEL;
    for (int d = lane; d < D_MODEL; d += 32) {
        float xv = xrow[d];
        const float4* wr = (const float4*)(gate_W + (size_t)d * NEXP);
#pragma unroll
        for (int q = 0; q < 4; q++) {
            float4 w4 = wr[q];
            acc[q * 4 + 0] = fmaf(xv, w4.x, acc[q * 4 + 0]);
            acc[q * 4 + 1] = fmaf(xv, w4.y, acc[q * 4 + 1]);
            acc[q * 4 + 2] = fmaf(xv, w4.z, acc[q * 4 + 2]);
            acc[q * 4 + 3] = fmaf(xv, w4.w, acc[q * 4 + 3]);
        }
    }
#pragma unroll
    for (int e = 0; e < NEXP; e++)
#pragma unroll
        for (int off = 16; off > 0; off >>= 1)
            acc[e] += __shfl_down_sync(0xffffffffu, acc[e], off);

    if (lane == 0) {
        float v0 = neg_inf(), v1 = neg_inf();
        int i0 = -1, i1 = -1;
#pragma unroll
        for (int e = 0; e < NEXP; e++) {
            float l = acc[e] + gate_b[e];
            if (l > v0)      { v1 = v0; i1 = i0; v0 = l; i0 = e; }
            else if (l > v1) { v1 = l; i1 = e; }
        }
        float t = expf(v1 - v0);
        float gw0 = 1.f / (1.f + t);
        float gw1 = t / (1.f + t);
        g_g[n * 2 + 0] = gw0;  g_gi[n * 2 + 0] = i0;
        g_g[n * 2 + 1] = gw1;  g_gi[n * 2 + 1] = i1;
        int p0 = atomicAdd(&g_cnt[i0], 1);
        g_btok[i0 * N_TOK + p0] = n;  g_bw[i0 * N_TOK + p0] = gw0;
        int p1 = atomicAdd(&g_cnt[i1], 1);
        g_btok[i1 * N_TOK + p1] = n;  g_bw[i1 * N_TOK + p1] = gw1;
    }
}

// ---------------- init output with gated expert biases ----------------
__global__ void __launch_bounds__(256) out_init_kernel(const float* __restrict__ expert_b,
                                                        float* __restrict__ out)
{
    const int n = blockIdx.x;
    const int tid = threadIdx.x;
    float gw0 = g_g[n * 2], gw1 = g_g[n * 2 + 1];
    int e0 = g_gi[n * 2], e1 = g_gi[n * 2 + 1];
    float4 b0 = *(const float4*)(expert_b + (size_t)e0 * DOUT + tid * 4);
    float4 b1 = *(const float4*)(expert_b + (size_t)e1 * DOUT + tid * 4);
    float4 o;
    o.x = gw0 * b0.x + gw1 * b1.x;
    o.y = gw0 * b0.y + gw1 * b1.y;
    o.z = gw0 * b0.z + gw1 * b1.z;
    o.w = gw0 * b0.w + gw1 * b1.w;
    *(float4*)(out + (size_t)n * DOUT + tid * 4) = o;
}

// ---------------- grouped expert GEMM via tf32 wmma ----------------
// Block 128(M)x64(N), 8 warps in 4(M)x2(N); warp tile 32x32 = 2x2 frags.
// Dynamic smem: As[128][24] + Bs[16][72] (phase 1) aliased with Cs[128][68] (epilogue).
#define EXP_SMEM_FLOATS  8704   // max(128*24 + 16*72 = 4224, 128*68 = 8704)

__global__ void __launch_bounds__(256) wmma_expert_kernel(const float* __restrict__ expert_W,
                                                           float* __restrict__ out)
{
    extern __shared__ float smem[];
    float (*As)[24] = (float(*)[24])smem;
    float (*Bs)[72] = (float(*)[72])(smem + 128 * 24);
    float (*Cs)[68] = (float(*)[68])smem;

    const int e = blockIdx.y;
    const int cnt = g_cnt[e];
    const int m0 = blockIdx.z * 128;
    if (m0 >= cnt) return;
    const int n0 = blockIdx.x * 64;

    __shared__ int   s_tok[128];
    __shared__ float s_gw[128];

    const int tid = threadIdx.x;
    const int warp = tid >> 5;
    const int wm = warp >> 1;              // 0..3
    const int wn = warp & 1;               // 0..1

    if (tid < 128) {
        int mi = m0 + tid;
        int ok = (mi < cnt);
        int src = ok ? mi : 0;
        s_tok[tid] = g_btok[e * N_TOK + src];
        s_gw[tid]  = ok ? g_bw[e * N_TOK + src] : 0.f;
    }
    __syncthreads();

    const float* W = expert_W + (size_t)e * D_MODEL * DOUT;

    wmma::fragment<wmma::accumulator, 16, 16, 8, float> acc[2][2];
#pragma unroll
    for (int i = 0; i < 2; i++)
#pragma unroll
        for (int j = 0; j < 2; j++) wmma::fill_fragment(acc[i][j], 0.f);

    for (int k0 = 0; k0 < D_MODEL; k0 += 16) {
        // A tile: gathered token rows, 128 x 16
#pragma unroll
        for (int l = tid; l < 512; l += 256) {
            int m = l >> 2, q = (l & 3) << 2;
            *(float4*)&As[m][q] = *(const float4*)(g_x + (size_t)s_tok[m] * D_MODEL + k0 + q);
        }
        // B tile: 16 x 64
        {
            int kr = tid >> 4, nc = (tid & 15) << 2;
            *(float4*)&Bs[kr][nc] = *(const float4*)(W + (size_t)(k0 + kr) * DOUT + n0 + nc);
        }
        __syncthreads();

#pragma unroll
        for (int kk = 0; kk < 16; kk += 8) {
            wmma::fragment<wmma::matrix_a, 16, 16, 8, wmma::precision::tf32, wmma::row_major> af[2];
#pragma unroll
            for (int i = 0; i < 2; i++) {
                wmma::load_matrix_sync(af[i], &As[wm * 32 + i * 16][kk], 24);
                to_tf32(af[i]);
            }
            wmma::fragment<wmma::matrix_b, 16, 16, 8, wmma::precision::tf32, wmma::row_major> bf[2];
#pragma unroll
            for (int j = 0; j < 2; j++) {
                wmma::load_matrix_sync(bf[j], &Bs[kk][wn * 32 + j * 16], 72);
                to_tf32(bf[j]);
            }
#pragma unroll
            for (int i = 0; i < 2; i++)
#pragma unroll
                for (int j = 0; j < 2; j++)
                    wmma::mma_sync(acc[i][j], af[i], bf[j], acc[i][j]);
        }
        __syncthreads();
    }

    // epilogue: stage to shared (aliases As/Bs), then gated scatter with atomics
#pragma unroll
    for (int i = 0; i < 2; i++)
#pragma unroll
        for (int j = 0; j < 2; j++)
            wmma::store_matrix_sync(&Cs[wm * 32 + i * 16][wn * 32 + j * 16],
                                    acc[i][j], 68, wmma::mem_row_major);
    __syncthreads();

#pragma unroll
    for (int l = tid; l < 2048; l += 256) {
        int m = l >> 4, c = (l & 15) << 2;
        if (m0 + m < cnt) {
            float gw = s_gw[m];
            float4 v = *(float4*)&Cs[m][c];
            float* op = out + (size_t)s_tok[m] * DOUT + n0 + c;
            atomicAdd(op + 0, gw * v.x);
            atomicAdd(op + 1, gw * v.y);
            atomicAdd(op + 2, gw * v.z);
            atomicAdd(op + 3, gw * v.w);
        }
    }
}

// ---------------- launch ----------------
extern "C" void kernel_launch(void* const* d_in, const int* in_sizes, int n_in,
                              void* d_out, int out_size)
{
    const float* data     = (const float*)d_in[0];  // [2048,1024]
    const float* W_q      = (const float*)d_in[1];  // [1024,2048]
    const float* keys     = (const float*)d_in[2];  // [4,2,256,256]
    const float* values   = (const float*)d_in[3];  // [65536,1024]
    const float* gate_W   = (const float*)d_in[4];  // [1024,16]
    const float* gate_b   = (const float*)d_in[5];  // [16]
    const float* expert_W = (const float*)d_in[6];  // [16,1024,1024]
    const float* expert_b = (const float*)d_in[7];  // [16,1024]
    float* out = (float*)d_out;                     // [2048,1024]

    float* dM; cudaGetSymbolAddress((void**)&dM, g_M);

    zero_cnt_kernel<<<1, 32>>>();

    // combined key projection: M[:, hc*256 + k] = W_q[:, hc] @ keys[hc]^T  (fp32 SIMT)
    sgemm128_tb<<<dim3(2, 8, HC), 256>>>(W_q, keys, dM,
                                         /*K=*/HALFD, /*lda=*/SCOLS, /*ldb=*/HALFD,
                                         /*ldc=*/SCOLS,
                                         /*zA=*/HALFD, /*zB=*/(long)NKEYS * HALFD,
                                         /*zC=*/NKEYS);

    // scores = data @ M   [2048 x 2048], K = 1024  (tf32 tensor cores)
    wmma_scores_kernel<<<dim3(SCOLS / 128, N_TOK / 128), 256>>>(data);

    // warp-per-(token,head) top-k: 8192 warps, 8 warps/block
    pkm_topk_warp_kernel<<<N_TOK * H_PKM / 8, 256>>>();
    pkm_gather_kernel<<<N_TOK, 256>>>(data, values);
    gate_kernel<<<N_TOK / 8, 256>>>(gate_W, gate_b);
    out_init_kernel<<<N_TOK, 256>>>(expert_b, out);

    // grouped expert GEMM (tf32 tensor cores)
    wmma_expert_kernel<<<dim3(DOUT / 64, NEXP, N_TOK / 128), 256,
                         EXP_SMEM_FLOATS * sizeof(float)>>>(expert_W, out);
}